// round 1
// baseline (speedup 1.0000x reference)
#include <cuda_runtime.h>
#include <math.h>

// Problem constants (sizes verified against in_sizes at runtime).
#define MAXN 50000
#define MAXE 800000
#define CIN0 128
#define COUT 64
#define NEG_SLOPE 0.2f

// ---------------- device scratch (no allocations allowed) ----------------
__device__ float g_hp[MAXN * COUT];     // h @ W for current layer
__device__ float g_h [MAXN * COUT];     // layer activation buffer
__device__ float g_as[MAXN];            // alpha_src per node
__device__ float g_ad[MAXN];            // alpha_dst per node
__device__ int   g_rowptr[MAXN + 1];
__device__ int   g_deg[MAXN];
__device__ int   g_cnt[MAXN];
__device__ int   g_esrc[MAXE];          // src node per edge, grouped by dst (CSR)

// ---------------- CSR build ----------------
__global__ void zero_kernel(int n) {
    int i = blockIdx.x * blockDim.x + threadIdx.x;
    if (i < n) { g_deg[i] = 0; g_cnt[i] = 0; }
}

__global__ void count_kernel(const int* __restrict__ ei, int E) {
    int i = blockIdx.x * blockDim.x + threadIdx.x;
    if (i < E) {
        int dst = ei[E + i];
        atomicAdd(&g_deg[dst], 1);
    }
}

__global__ void scan_kernel(int n) {
    __shared__ int sums[1024];
    int t = threadIdx.x;
    int chunk = (n + 1023) / 1024;
    int s0 = t * chunk;
    int s1 = min(n, s0 + chunk);
    int s = 0;
    for (int i = s0; i < s1; i++) s += g_deg[i];
    sums[t] = s;
    __syncthreads();
    // Hillis-Steele inclusive scan
    for (int off = 1; off < 1024; off <<= 1) {
        int v = (t >= off) ? sums[t - off] : 0;
        __syncthreads();
        sums[t] += v;
        __syncthreads();
    }
    int run = (t > 0) ? sums[t - 1] : 0;
    for (int i = s0; i < s1; i++) { g_rowptr[i] = run; run += g_deg[i]; }
    if (t == 1023) g_rowptr[n] = sums[1023];
}

__global__ void scatter_kernel(const int* __restrict__ ei, int E) {
    int i = blockIdx.x * blockDim.x + threadIdx.x;
    if (i < E) {
        int src = ei[i];
        int dst = ei[E + i];
        int pos = g_rowptr[dst] + atomicAdd(&g_cnt[dst], 1);
        g_esrc[pos] = src;
    }
}

// ---------------- GEMM: hp = h @ W  (cin x 64 weight in smem) ----------------
// block: 64x8 threads, block covers 32 rows x 64 cols, each thread: 4 rows.
__global__ void gemm_kernel(const float* __restrict__ Xext, int use_ext,
                            const float* __restrict__ W, int n, int cin) {
    __shared__ float Ws[CIN0 * COUT];
    const float* X = use_ext ? Xext : g_h;
    int col = threadIdx.x;          // 0..63
    int ty  = threadIdx.y;          // 0..7
    int tid = ty * 64 + col;
    for (int i = tid; i < cin * COUT; i += 512) Ws[i] = W[i];
    __syncthreads();

    int row0 = blockIdx.x * 32 + ty * 4;
    float acc0 = 0.f, acc1 = 0.f, acc2 = 0.f, acc3 = 0.f;
    int r0 = min(row0 + 0, n - 1);
    int r1 = min(row0 + 1, n - 1);
    int r2 = min(row0 + 2, n - 1);
    int r3 = min(row0 + 3, n - 1);
    const float* x0 = X + (size_t)r0 * cin;
    const float* x1 = X + (size_t)r1 * cin;
    const float* x2 = X + (size_t)r2 * cin;
    const float* x3 = X + (size_t)r3 * cin;

    #pragma unroll 4
    for (int k = 0; k < cin; k++) {
        float w = Ws[k * COUT + col];
        acc0 = fmaf(x0[k], w, acc0);
        acc1 = fmaf(x1[k], w, acc1);
        acc2 = fmaf(x2[k], w, acc2);
        acc3 = fmaf(x3[k], w, acc3);
    }
    if (row0 + 0 < n) g_hp[(size_t)(row0 + 0) * COUT + col] = acc0;
    if (row0 + 1 < n) g_hp[(size_t)(row0 + 1) * COUT + col] = acc1;
    if (row0 + 2 < n) g_hp[(size_t)(row0 + 2) * COUT + col] = acc2;
    if (row0 + 3 < n) g_hp[(size_t)(row0 + 3) * COUT + col] = acc3;
}

// ---------------- alpha: per-node dot(hp, a_src) and dot(hp, a_dst) ----------------
// warp per node, 2 channels per lane
__global__ void alpha_kernel(const float* __restrict__ a_src,
                             const float* __restrict__ a_dst, int n) {
    int gwarp = (blockIdx.x * blockDim.x + threadIdx.x) >> 5;
    int lane  = threadIdx.x & 31;
    if (gwarp >= n) return;
    float v0 = g_hp[(size_t)gwarp * COUT + lane];
    float v1 = g_hp[(size_t)gwarp * COUT + 32 + lane];
    float s = v0 * __ldg(&a_src[lane]) + v1 * __ldg(&a_src[32 + lane]);
    float d = v0 * __ldg(&a_dst[lane]) + v1 * __ldg(&a_dst[32 + lane]);
    #pragma unroll
    for (int off = 16; off > 0; off >>= 1) {
        s += __shfl_xor_sync(0xffffffffu, s, off);
        d += __shfl_xor_sync(0xffffffffu, d, off);
    }
    if (lane == 0) { g_as[gwarp] = s; g_ad[gwarp] = d; }
}

__device__ __forceinline__ float leaky(float e) {
    return e > 0.f ? e : NEG_SLOPE * e;
}

// ---------------- aggregation: warp per dst node, softmax over incoming + self ----------------
__global__ void aggregate_kernel(const float* __restrict__ bias,
                                 float* __restrict__ out_ext, int to_ext, int n) {
    int gwarp = (blockIdx.x * blockDim.x + threadIdx.x) >> 5;
    int lane  = threadIdx.x & 31;
    if (gwarp >= n) return;
    int node  = gwarp;
    int start = g_rowptr[node];
    int end   = g_rowptr[node + 1];
    float ad_n = g_ad[node];
    float e_self = leaky(g_as[node] + ad_n);

    // pass 1: max
    float m = e_self;
    for (int j = start + lane; j < end; j += 32) {
        float e = leaky(g_as[g_esrc[j]] + ad_n);
        m = fmaxf(m, e);
    }
    #pragma unroll
    for (int off = 16; off > 0; off >>= 1)
        m = fmaxf(m, __shfl_xor_sync(0xffffffffu, m, off));

    // pass 2: sum of exp
    float s = 0.f;
    for (int j = start + lane; j < end; j += 32) {
        float e = leaky(g_as[g_esrc[j]] + ad_n);
        s += __expf(e - m);
    }
    #pragma unroll
    for (int off = 16; off > 0; off >>= 1)
        s += __shfl_xor_sync(0xffffffffu, s, off);
    s += __expf(e_self - m);
    float inv = 1.f / (s + 1e-16f);

    // pass 3: weighted message accumulation; lanes own channels {lane, lane+32}
    float w_self = __expf(e_self - m) * inv;
    float acc0 = w_self * g_hp[(size_t)node * COUT + lane];
    float acc1 = w_self * g_hp[(size_t)node * COUT + 32 + lane];

    for (int j0 = start; j0 < end; j0 += 32) {
        int jj = j0 + lane;
        int cnt = min(32, end - j0);
        int src = 0; float w = 0.f;
        if (jj < end) {
            src = g_esrc[jj];
            float e = leaky(g_as[src] + ad_n);
            w = __expf(e - m) * inv;
        }
        for (int t = 0; t < cnt; t++) {
            float wt = __shfl_sync(0xffffffffu, w, t);
            int   st = __shfl_sync(0xffffffffu, src, t);
            const float* hrow = &g_hp[(size_t)st * COUT];
            acc0 = fmaf(wt, hrow[lane], acc0);
            acc1 = fmaf(wt, hrow[32 + lane], acc1);
        }
    }

    float o0 = acc0 + __ldg(&bias[lane]);
    float o1 = acc1 + __ldg(&bias[32 + lane]);
    o0 = o0 > 0.f ? o0 : 0.f;   // relu
    o1 = o1 > 0.f ? o1 : 0.f;
    float* out = to_ext ? out_ext : g_h;
    out[(size_t)node * COUT + lane]      = o0;
    out[(size_t)node * COUT + 32 + lane] = o1;
}

// ---------------- host launcher ----------------
extern "C" void kernel_launch(void* const* d_in, const int* in_sizes, int n_in,
                              void* d_out, int out_size) {
    const float* x  = (const float*)d_in[0];
    const int*   ei = (const int*)  d_in[1];
    // d_in[2] = batch_size, d_in[3] = framework (unused, framework=1 path)
    const float* W0 = (const float*)d_in[4];
    const float* as0 = (const float*)d_in[5];
    const float* ad0 = (const float*)d_in[6];
    const float* b0  = (const float*)d_in[7];
    const float* W1 = (const float*)d_in[8];
    const float* as1 = (const float*)d_in[9];
    const float* ad1 = (const float*)d_in[10];
    const float* b1  = (const float*)d_in[11];
    const float* W2 = (const float*)d_in[12];
    const float* as2 = (const float*)d_in[13];
    const float* ad2 = (const float*)d_in[14];
    const float* b2  = (const float*)d_in[15];

    int n = in_sizes[0] / CIN0;   // 50000
    int E = in_sizes[1] / 2;      // 800000
    float* out = (float*)d_out;

    // ---- CSR build (once; shared by all 3 layers) ----
    zero_kernel   <<<(n + 255) / 256, 256>>>(n);
    count_kernel  <<<(E + 255) / 256, 256>>>(ei, E);
    scan_kernel   <<<1, 1024>>>(n);
    scatter_kernel<<<(E + 255) / 256, 256>>>(ei, E);

    dim3 gblock(64, 8);
    int ggrid = (n + 31) / 32;
    int wgrid = (n + 7) / 8;      // 8 warps/block of 256 threads

    // ---- layer 0 : x(128) -> g_h(64) ----
    gemm_kernel     <<<ggrid, gblock>>>(x, 1, W0, n, CIN0);
    alpha_kernel    <<<wgrid, 256>>>(as0, ad0, n);
    aggregate_kernel<<<wgrid, 256>>>(b0, nullptr, 0, n);

    // ---- layer 1 : g_h(64) -> g_h(64) ----
    gemm_kernel     <<<ggrid, gblock>>>(nullptr, 0, W1, n, COUT);
    alpha_kernel    <<<wgrid, 256>>>(as1, ad1, n);
    aggregate_kernel<<<wgrid, 256>>>(b1, nullptr, 0, n);

    // ---- layer 2 : g_h(64) -> d_out(64) ----
    gemm_kernel     <<<ggrid, gblock>>>(nullptr, 0, W2, n, COUT);
    alpha_kernel    <<<wgrid, 256>>>(as2, ad2, n);
    aggregate_kernel<<<wgrid, 256>>>(b2, out, 1, n);
}

// round 2
// speedup vs baseline: 1.2926x; 1.2926x over previous
#include <cuda_runtime.h>
#include <math.h>

#define MAXN 50000
#define MAXE 800000
#define CIN0 128
#define COUT 64
#define NEG_SLOPE 0.2f

// ---------------- device scratch ----------------
__device__ float2 g_hp2[MAXN * 32];     // h @ W, PERMUTED: pos 2l,2l+1 = channels l, l+32
__device__ float2 g_h2 [MAXN * 32];     // layer activations, same permuted layout
__device__ float  g_as[MAXN];
__device__ float  g_ad[MAXN];
__device__ int    g_rowptr[MAXN + 1];
__device__ int    g_deg[MAXN];
__device__ int    g_cnt[MAXN];
__device__ int    g_esrc[MAXE];

// ---------------- packed f32x2 helpers ----------------
__device__ __forceinline__ float2 ffma2(float2 a, float2 b, float2 c) {
    unsigned long long ra = *(unsigned long long*)&a;
    unsigned long long rb = *(unsigned long long*)&b;
    unsigned long long rc = *(unsigned long long*)&c;
    unsigned long long rd;
    asm("fma.rn.f32x2 %0, %1, %2, %3;" : "=l"(rd) : "l"(ra), "l"(rb), "l"(rc));
    return *(float2*)&rd;
}
__device__ __forceinline__ float2 dup2(float x) { return make_float2(x, x); }

// ---------------- CSR build ----------------
__global__ void zero_kernel(int n) {
    int i = blockIdx.x * blockDim.x + threadIdx.x;
    if (i < n) { g_deg[i] = 0; g_cnt[i] = 0; }
}

__global__ void count_kernel(const int* __restrict__ ei, int E) {
    int i = blockIdx.x * blockDim.x + threadIdx.x;
    if (i < E) atomicAdd(&g_deg[ei[E + i]], 1);
}

__global__ void scan_kernel(int n) {
    __shared__ int sums[1024];
    int t = threadIdx.x;
    int chunk = (n + 1023) / 1024;
    int s0 = t * chunk;
    int s1 = min(n, s0 + chunk);
    int s = 0;
    for (int i = s0; i < s1; i++) s += g_deg[i];
    sums[t] = s;
    __syncthreads();
    for (int off = 1; off < 1024; off <<= 1) {
        int v = (t >= off) ? sums[t - off] : 0;
        __syncthreads();
        sums[t] += v;
        __syncthreads();
    }
    int run = (t > 0) ? sums[t - 1] : 0;
    for (int i = s0; i < s1; i++) { g_rowptr[i] = run; run += g_deg[i]; }
    if (t == 1023) g_rowptr[n] = sums[1023];
}

__global__ void scatter_kernel(const int* __restrict__ ei, int E) {
    int i = blockIdx.x * blockDim.x + threadIdx.x;
    if (i < E) {
        int src = ei[i];
        int dst = ei[E + i];
        int pos = g_rowptr[dst] + atomicAdd(&g_cnt[dst], 1);
        g_esrc[pos] = src;
    }
}

// ---------------- GEMM + fused alpha ----------------
// block (32,8): thread owns column pair (tx, tx+32), 4 rows. FFMA2 throughout.
// Writes hp2 permuted; computes alpha_src/alpha_dst per row in epilogue.
__global__ void gemm_alpha_kernel(const float4* __restrict__ X,
                                  const float* __restrict__ W,
                                  const float* __restrict__ a_src,
                                  const float* __restrict__ a_dst,
                                  int n, int cin, int permW) {
    __shared__ float2 Ws2[CIN0 * 32];   // 32 KB max
    int tx = threadIdx.x;               // 0..31 (column pair id)
    int ty = threadIdx.y;               // 0..7
    int tid = ty * 32 + tx;

    // fill weights: Ws2[k*32 + c] = { W[kk][c], W[kk][c+32] }
    for (int idx = tid; idx < cin * 32; idx += 256) {
        int k = idx >> 5, c = idx & 31;
        int kk = permW ? ((k >> 1) + ((k & 1) << 5)) : k;
        Ws2[idx] = make_float2(W[kk * 64 + c], W[kk * 64 + c + 32]);
    }
    __syncthreads();

    int row0 = blockIdx.x * 32 + ty * 4;
    int r0 = min(row0 + 0, n - 1);
    int r1 = min(row0 + 1, n - 1);
    int r2 = min(row0 + 2, n - 1);
    int r3 = min(row0 + 3, n - 1);
    const float4* x0 = X + (size_t)r0 * (cin >> 2);
    const float4* x1 = X + (size_t)r1 * (cin >> 2);
    const float4* x2 = X + (size_t)r2 * (cin >> 2);
    const float4* x3 = X + (size_t)r3 * (cin >> 2);

    float2 acc0 = make_float2(0.f, 0.f);
    float2 acc1 = make_float2(0.f, 0.f);
    float2 acc2 = make_float2(0.f, 0.f);
    float2 acc3 = make_float2(0.f, 0.f);

    int kq = cin >> 2;
    for (int k4 = 0; k4 < kq; k4++) {
        float4 v0 = x0[k4];
        float4 v1 = x1[k4];
        float4 v2 = x2[k4];
        float4 v3 = x3[k4];
        int kb = k4 * 4 * 32 + tx;
        float2 wA = Ws2[kb];
        float2 wB = Ws2[kb + 32];
        float2 wC = Ws2[kb + 64];
        float2 wD = Ws2[kb + 96];
        acc0 = ffma2(dup2(v0.x), wA, acc0);
        acc1 = ffma2(dup2(v1.x), wA, acc1);
        acc2 = ffma2(dup2(v2.x), wA, acc2);
        acc3 = ffma2(dup2(v3.x), wA, acc3);
        acc0 = ffma2(dup2(v0.y), wB, acc0);
        acc1 = ffma2(dup2(v1.y), wB, acc1);
        acc2 = ffma2(dup2(v2.y), wB, acc2);
        acc3 = ffma2(dup2(v3.y), wB, acc3);
        acc0 = ffma2(dup2(v0.z), wC, acc0);
        acc1 = ffma2(dup2(v1.z), wC, acc1);
        acc2 = ffma2(dup2(v2.z), wC, acc2);
        acc3 = ffma2(dup2(v3.z), wC, acc3);
        acc0 = ffma2(dup2(v0.w), wD, acc0);
        acc1 = ffma2(dup2(v1.w), wD, acc1);
        acc2 = ffma2(dup2(v2.w), wD, acc2);
        acc3 = ffma2(dup2(v3.w), wD, acc3);
    }

    // store hp permuted
    if (row0 + 0 < n) g_hp2[(size_t)(row0 + 0) * 32 + tx] = acc0;
    if (row0 + 1 < n) g_hp2[(size_t)(row0 + 1) * 32 + tx] = acc1;
    if (row0 + 2 < n) g_hp2[(size_t)(row0 + 2) * 32 + tx] = acc2;
    if (row0 + 3 < n) g_hp2[(size_t)(row0 + 3) * 32 + tx] = acc3;

    // fused alpha: each warp (fixed ty) spans all 64 columns of its 4 rows
    float asA = __ldg(&a_src[tx]), asB = __ldg(&a_src[tx + 32]);
    float adA = __ldg(&a_dst[tx]), adB = __ldg(&a_dst[tx + 32]);
    float s0 = acc0.x * asA + acc0.y * asB;
    float s1 = acc1.x * asA + acc1.y * asB;
    float s2 = acc2.x * asA + acc2.y * asB;
    float s3 = acc3.x * asA + acc3.y * asB;
    float d0 = acc0.x * adA + acc0.y * adB;
    float d1 = acc1.x * adA + acc1.y * adB;
    float d2 = acc2.x * adA + acc2.y * adB;
    float d3 = acc3.x * adA + acc3.y * adB;
    #pragma unroll
    for (int off = 16; off > 0; off >>= 1) {
        s0 += __shfl_xor_sync(0xffffffffu, s0, off);
        s1 += __shfl_xor_sync(0xffffffffu, s1, off);
        s2 += __shfl_xor_sync(0xffffffffu, s2, off);
        s3 += __shfl_xor_sync(0xffffffffu, s3, off);
        d0 += __shfl_xor_sync(0xffffffffu, d0, off);
        d1 += __shfl_xor_sync(0xffffffffu, d1, off);
        d2 += __shfl_xor_sync(0xffffffffu, d2, off);
        d3 += __shfl_xor_sync(0xffffffffu, d3, off);
    }
    if (tx == 0) {
        if (row0 + 0 < n) { g_as[row0 + 0] = s0; g_ad[row0 + 0] = d0; }
        if (row0 + 1 < n) { g_as[row0 + 1] = s1; g_ad[row0 + 1] = d1; }
        if (row0 + 2 < n) { g_as[row0 + 2] = s2; g_ad[row0 + 2] = d2; }
        if (row0 + 3 < n) { g_as[row0 + 3] = s3; g_ad[row0 + 3] = d3; }
    }
}

__device__ __forceinline__ float leaky(float e) {
    return e > 0.f ? e : NEG_SLOPE * e;
}

// ---------------- aggregation: warp per dst node ----------------
__global__ void aggregate_kernel(const float* __restrict__ bias,
                                 float* __restrict__ out_ext, int to_ext, int n) {
    int node = (blockIdx.x * blockDim.x + threadIdx.x) >> 5;
    int lane = threadIdx.x & 31;
    if (node >= n) return;
    int start = g_rowptr[node];
    int end   = g_rowptr[node + 1];
    float ad_n = g_ad[node];
    float e_self = leaky(g_as[node] + ad_n);

    // single-pass online softmax (m, s) per lane; lane0 seeds with self
    float m = (lane == 0) ? e_self : -1e30f;
    float s = (lane == 0) ? 1.f : 0.f;
    for (int j = start + lane; j < end; j += 32) {
        float e = leaky(g_as[g_esrc[j]] + ad_n);
        if (e > m) { s = s * __expf(m - e) + 1.f; m = e; }
        else       { s += __expf(e - m); }
    }
    #pragma unroll
    for (int off = 16; off > 0; off >>= 1) {
        float mo = __shfl_xor_sync(0xffffffffu, m, off);
        float so = __shfl_xor_sync(0xffffffffu, s, off);
        float mn = fmaxf(m, mo);
        s = s * __expf(m - mn) + so * __expf(mo - mn);
        m = mn;
    }
    float inv = 1.f / (s + 1e-16f);

    // gather pass: lane owns channel pair (lane, lane+32) stored as one float2
    float w_self = __expf(e_self - m) * inv;
    float2 vself = g_hp2[(size_t)node * 32 + lane];
    float2 acc = make_float2(w_self * vself.x, w_self * vself.y);

    for (int j0 = start; j0 < end; j0 += 32) {
        int jj = j0 + lane;
        int cnt = min(32, end - j0);
        int src = 0; float w = 0.f;
        if (jj < end) {
            src = g_esrc[jj];
            w = __expf(leaky(g_as[src] + ad_n) - m) * inv;
        }
        int t = 0;
        for (; t + 1 < cnt; t += 2) {
            float w0 = __shfl_sync(0xffffffffu, w, t);
            int   i0 = __shfl_sync(0xffffffffu, src, t);
            float w1 = __shfl_sync(0xffffffffu, w, t + 1);
            int   i1 = __shfl_sync(0xffffffffu, src, t + 1);
            float2 v0 = g_hp2[(size_t)i0 * 32 + lane];
            float2 v1 = g_hp2[(size_t)i1 * 32 + lane];
            acc = ffma2(dup2(w0), v0, acc);
            acc = ffma2(dup2(w1), v1, acc);
        }
        if (t < cnt) {
            float w0 = __shfl_sync(0xffffffffu, w, t);
            int   i0 = __shfl_sync(0xffffffffu, src, t);
            float2 v0 = g_hp2[(size_t)i0 * 32 + lane];
            acc = ffma2(dup2(w0), v0, acc);
        }
    }

    float o0 = acc.x + __ldg(&bias[lane]);
    float o1 = acc.y + __ldg(&bias[lane + 32]);
    o0 = o0 > 0.f ? o0 : 0.f;
    o1 = o1 > 0.f ? o1 : 0.f;
    if (to_ext) {
        out_ext[(size_t)node * 64 + lane]      = o0;   // un-permute
        out_ext[(size_t)node * 64 + 32 + lane] = o1;
    } else {
        g_h2[(size_t)node * 32 + lane] = make_float2(o0, o1);  // keep permuted
    }
}

// ---------------- host launcher ----------------
extern "C" void kernel_launch(void* const* d_in, const int* in_sizes, int n_in,
                              void* d_out, int out_size) {
    const float* x  = (const float*)d_in[0];
    const int*   ei = (const int*)  d_in[1];
    const float* W0 = (const float*)d_in[4];
    const float* as0 = (const float*)d_in[5];
    const float* ad0 = (const float*)d_in[6];
    const float* b0  = (const float*)d_in[7];
    const float* W1 = (const float*)d_in[8];
    const float* as1 = (const float*)d_in[9];
    const float* ad1 = (const float*)d_in[10];
    const float* b1  = (const float*)d_in[11];
    const float* W2 = (const float*)d_in[12];
    const float* as2 = (const float*)d_in[13];
    const float* ad2 = (const float*)d_in[14];
    const float* b2  = (const float*)d_in[15];

    int n = in_sizes[0] / CIN0;
    int E = in_sizes[1] / 2;
    float* out = (float*)d_out;

    // CSR build (shared by all layers)
    zero_kernel   <<<(n + 255) / 256, 256>>>(n);
    count_kernel  <<<(E + 255) / 256, 256>>>(ei, E);
    scan_kernel   <<<1, 1024>>>(n);
    scatter_kernel<<<(E + 255) / 256, 256>>>(ei, E);

    dim3 gblock(32, 8);
    int ggrid = (n + 31) / 32;
    int wgrid = (n + 7) / 8;

    float2* h2 = nullptr;
    cudaGetSymbolAddress((void**)&h2, g_h2);

    // layer 0: x(128) -> g_h2
    gemm_alpha_kernel<<<ggrid, gblock>>>((const float4*)x, W0, as0, ad0, n, CIN0, 0);
    aggregate_kernel <<<wgrid, 256>>>(b0, nullptr, 0, n);

    // layer 1: g_h2 -> g_h2
    gemm_alpha_kernel<<<ggrid, gblock>>>((const float4*)h2, W1, as1, ad1, n, COUT, 1);
    aggregate_kernel <<<wgrid, 256>>>(b1, nullptr, 0, n);

    // layer 2: g_h2 -> out
    gemm_alpha_kernel<<<ggrid, gblock>>>((const float4*)h2, W2, as2, ad2, n, COUT, 1);
    aggregate_kernel <<<wgrid, 256>>>(b2, out, 1, n);
}

// round 3
// speedup vs baseline: 1.3192x; 1.0205x over previous
#include <cuda_runtime.h>
#include <math.h>

#define MAXN 50000
#define MAXE 800000
#define CIN0 128
#define COUT 64
#define NEG_SLOPE 0.2f

// ---------------- device scratch ----------------
__device__ float2 g_hp2[MAXN * 32];     // h @ W, PERMUTED: pos l = channels (l, l+32)
__device__ float2 g_h2 [MAXN * 32];     // layer activations, same permuted layout
__device__ float  g_as[MAXN];
__device__ float  g_ad[MAXN];
__device__ int    g_rowptr[MAXN + 1];
__device__ int    g_deg[MAXN];
__device__ int    g_cnt[MAXN];          // mutable copy of rowptr starts
__device__ int    g_esrc[MAXE];

// ---------------- packed f32x2 helpers ----------------
__device__ __forceinline__ float2 ffma2(float2 a, float2 b, float2 c) {
    unsigned long long ra = *(unsigned long long*)&a;
    unsigned long long rb = *(unsigned long long*)&b;
    unsigned long long rc = *(unsigned long long*)&c;
    unsigned long long rd;
    asm("fma.rn.f32x2 %0, %1, %2, %3;" : "=l"(rd) : "l"(ra), "l"(rb), "l"(rc));
    return *(float2*)&rd;
}
__device__ __forceinline__ float2 dup2(float x) { return make_float2(x, x); }

__device__ __forceinline__ float leaky(float e) {
    return e > 0.f ? e : NEG_SLOPE * e;
}

// ---------------- GEMM + fused alpha (+ optional fused degree count) ----------------
// gemm blocks: (32,8) logical; thread owns column pair (tx, tx+32), 4 rows.
// blocks [ggrid, ggrid+cgrid) do the edge-degree count instead (layer 0 only).
__global__ void gemm_alpha_kernel(const float4* __restrict__ X,
                                  const float* __restrict__ W,
                                  const float* __restrict__ a_src,
                                  const float* __restrict__ a_dst,
                                  int n, int cin, int permW,
                                  const int* __restrict__ ei, int E, int ggrid) {
    // ---- fused count part (independent of GEMM; hides atomic latency) ----
    if (blockIdx.x >= ggrid) {
        int base = (blockIdx.x - ggrid) * 1024 + (threadIdx.y * 32 + threadIdx.x);
        #pragma unroll
        for (int u = 0; u < 4; u++) {
            int i = base + u * 256;
            if (i < E) atomicAdd(&g_deg[__ldg(&ei[E + i])], 1);
        }
        return;
    }

    __shared__ float2 Ws2[CIN0 * 32];
    int tx = threadIdx.x;               // 0..31
    int ty = threadIdx.y;               // 0..7
    int tid = ty * 32 + tx;

    for (int idx = tid; idx < cin * 32; idx += 256) {
        int k = idx >> 5, c = idx & 31;
        int kk = permW ? ((k >> 1) + ((k & 1) << 5)) : k;
        Ws2[idx] = make_float2(W[kk * 64 + c], W[kk * 64 + c + 32]);
    }
    __syncthreads();

    int row0 = blockIdx.x * 32 + ty * 4;
    int r0 = min(row0 + 0, n - 1);
    int r1 = min(row0 + 1, n - 1);
    int r2 = min(row0 + 2, n - 1);
    int r3 = min(row0 + 3, n - 1);
    const float4* x0 = X + (size_t)r0 * (cin >> 2);
    const float4* x1 = X + (size_t)r1 * (cin >> 2);
    const float4* x2 = X + (size_t)r2 * (cin >> 2);
    const float4* x3 = X + (size_t)r3 * (cin >> 2);

    float2 acc0 = make_float2(0.f, 0.f);
    float2 acc1 = make_float2(0.f, 0.f);
    float2 acc2 = make_float2(0.f, 0.f);
    float2 acc3 = make_float2(0.f, 0.f);

    int kq = cin >> 2;
    for (int k4 = 0; k4 < kq; k4++) {
        float4 v0 = x0[k4];
        float4 v1 = x1[k4];
        float4 v2 = x2[k4];
        float4 v3 = x3[k4];
        int kb = k4 * 4 * 32 + tx;
        float2 wA = Ws2[kb];
        float2 wB = Ws2[kb + 32];
        float2 wC = Ws2[kb + 64];
        float2 wD = Ws2[kb + 96];
        acc0 = ffma2(dup2(v0.x), wA, acc0);
        acc1 = ffma2(dup2(v1.x), wA, acc1);
        acc2 = ffma2(dup2(v2.x), wA, acc2);
        acc3 = ffma2(dup2(v3.x), wA, acc3);
        acc0 = ffma2(dup2(v0.y), wB, acc0);
        acc1 = ffma2(dup2(v1.y), wB, acc1);
        acc2 = ffma2(dup2(v2.y), wB, acc2);
        acc3 = ffma2(dup2(v3.y), wB, acc3);
        acc0 = ffma2(dup2(v0.z), wC, acc0);
        acc1 = ffma2(dup2(v1.z), wC, acc1);
        acc2 = ffma2(dup2(v2.z), wC, acc2);
        acc3 = ffma2(dup2(v3.z), wC, acc3);
        acc0 = ffma2(dup2(v0.w), wD, acc0);
        acc1 = ffma2(dup2(v1.w), wD, acc1);
        acc2 = ffma2(dup2(v2.w), wD, acc2);
        acc3 = ffma2(dup2(v3.w), wD, acc3);
    }

    if (row0 + 0 < n) g_hp2[(size_t)(row0 + 0) * 32 + tx] = acc0;
    if (row0 + 1 < n) g_hp2[(size_t)(row0 + 1) * 32 + tx] = acc1;
    if (row0 + 2 < n) g_hp2[(size_t)(row0 + 2) * 32 + tx] = acc2;
    if (row0 + 3 < n) g_hp2[(size_t)(row0 + 3) * 32 + tx] = acc3;

    float asA = __ldg(&a_src[tx]), asB = __ldg(&a_src[tx + 32]);
    float adA = __ldg(&a_dst[tx]), adB = __ldg(&a_dst[tx + 32]);
    float s0 = acc0.x * asA + acc0.y * asB;
    float s1 = acc1.x * asA + acc1.y * asB;
    float s2 = acc2.x * asA + acc2.y * asB;
    float s3 = acc3.x * asA + acc3.y * asB;
    float d0 = acc0.x * adA + acc0.y * adB;
    float d1 = acc1.x * adA + acc1.y * adB;
    float d2 = acc2.x * adA + acc2.y * adB;
    float d3 = acc3.x * adA + acc3.y * adB;
    #pragma unroll
    for (int off = 16; off > 0; off >>= 1) {
        s0 += __shfl_xor_sync(0xffffffffu, s0, off);
        s1 += __shfl_xor_sync(0xffffffffu, s1, off);
        s2 += __shfl_xor_sync(0xffffffffu, s2, off);
        s3 += __shfl_xor_sync(0xffffffffu, s3, off);
        d0 += __shfl_xor_sync(0xffffffffu, d0, off);
        d1 += __shfl_xor_sync(0xffffffffu, d1, off);
        d2 += __shfl_xor_sync(0xffffffffu, d2, off);
        d3 += __shfl_xor_sync(0xffffffffu, d3, off);
    }
    if (tx == 0) {
        if (row0 + 0 < n) { g_as[row0 + 0] = s0; g_ad[row0 + 0] = d0; }
        if (row0 + 1 < n) { g_as[row0 + 1] = s1; g_ad[row0 + 1] = d1; }
        if (row0 + 2 < n) { g_as[row0 + 2] = s2; g_ad[row0 + 2] = d2; }
        if (row0 + 3 < n) { g_as[row0 + 3] = s3; g_ad[row0 + 3] = d3; }
    }
}

// ---------------- two-level coalesced exclusive scan (1 block, 1024 thr) ----------------
// writes g_rowptr (exclusive starts) and g_cnt (mutable copy for scatter)
__global__ void scan_kernel(int n) {
    __shared__ int wsum[32];
    __shared__ int carry_s;
    int t = threadIdx.x, lane = t & 31, wid = t >> 5;
    if (t == 0) carry_s = 0;
    __syncthreads();
    for (int base = 0; base < n; base += 1024) {
        int i = base + t;
        int v = (i < n) ? g_deg[i] : 0;
        int s = v;
        #pragma unroll
        for (int off = 1; off < 32; off <<= 1) {
            int u = __shfl_up_sync(0xffffffffu, s, off);
            if (lane >= off) s += u;
        }
        if (lane == 31) wsum[wid] = s;
        __syncthreads();
        if (wid == 0) {
            int ws = wsum[lane];
            #pragma unroll
            for (int off = 1; off < 32; off <<= 1) {
                int u = __shfl_up_sync(0xffffffffu, ws, off);
                if (lane >= off) ws += u;
            }
            wsum[lane] = ws;
        }
        __syncthreads();
        int woff = (wid > 0) ? wsum[wid - 1] : 0;
        int carry = carry_s;
        int excl = carry + woff + s - v;
        if (i < n) { g_rowptr[i] = excl; g_cnt[i] = excl; }
        __syncthreads();
        if (t == 1023) carry_s = carry + woff + s;
        __syncthreads();
    }
    if (t == 0) g_rowptr[n] = carry_s;
}

__global__ void scatter_kernel(const int* __restrict__ ei, int E) {
    int base = (blockIdx.x * blockDim.x + threadIdx.x) * 2;
    #pragma unroll
    for (int u = 0; u < 2; u++) {
        int i = base + u;
        if (i < E) {
            int src = __ldg(&ei[i]);
            int dst = __ldg(&ei[E + i]);
            int pos = atomicAdd(&g_cnt[dst], 1);
            g_esrc[pos] = src;
        }
    }
}

// ---------------- gather helper: broadcast (w, src) over valid lanes ----------------
__device__ __forceinline__ void gather32(float w, int src, int cnt, int lane, float2& acc) {
    int t = 0;
    for (; t + 3 < cnt; t += 4) {
        float w0 = __shfl_sync(0xffffffffu, w, t);
        float w1 = __shfl_sync(0xffffffffu, w, t + 1);
        float w2 = __shfl_sync(0xffffffffu, w, t + 2);
        float w3 = __shfl_sync(0xffffffffu, w, t + 3);
        int i0 = __shfl_sync(0xffffffffu, src, t);
        int i1 = __shfl_sync(0xffffffffu, src, t + 1);
        int i2 = __shfl_sync(0xffffffffu, src, t + 2);
        int i3 = __shfl_sync(0xffffffffu, src, t + 3);
        float2 v0 = g_hp2[(size_t)i0 * 32 + lane];
        float2 v1 = g_hp2[(size_t)i1 * 32 + lane];
        float2 v2 = g_hp2[(size_t)i2 * 32 + lane];
        float2 v3 = g_hp2[(size_t)i3 * 32 + lane];
        acc = ffma2(dup2(w0), v0, acc);
        acc = ffma2(dup2(w1), v1, acc);
        acc = ffma2(dup2(w2), v2, acc);
        acc = ffma2(dup2(w3), v3, acc);
    }
    for (; t < cnt; t++) {
        float w0 = __shfl_sync(0xffffffffu, w, t);
        int   i0 = __shfl_sync(0xffffffffu, src, t);
        float2 v0 = g_hp2[(size_t)i0 * 32 + lane];
        acc = ffma2(dup2(w0), v0, acc);
    }
}

// ---------------- aggregation: warp per dst node ----------------
__global__ void aggregate_kernel(const float* __restrict__ bias,
                                 float* __restrict__ out_ext, int to_ext, int n) {
    int node = (blockIdx.x * blockDim.x + threadIdx.x) >> 5;
    int lane = threadIdx.x & 31;
    if (node >= n) return;
    int start = g_rowptr[node];
    int end   = g_rowptr[node + 1];
    float ad_n = g_ad[node];
    float e_self = leaky(g_as[node] + ad_n);

    // --- online softmax; cache first-chunk (src, e) in registers ---
    float m = (lane == 0) ? e_self : -1e30f;
    float s = (lane == 0) ? 1.f : 0.f;
    int   src_c = 0;
    float e_c   = 0.f;
    int j0lane = start + lane;
    if (j0lane < end) {
        src_c = __ldg(&g_esrc[j0lane]);
        e_c = leaky(g_as[src_c] + ad_n);
        if (e_c > m) { s = s * __expf(m - e_c) + 1.f; m = e_c; }
        else         { s += __expf(e_c - m); }
    }
    for (int j = j0lane + 32; j < end; j += 32) {
        float e = leaky(g_as[__ldg(&g_esrc[j])] + ad_n);
        if (e > m) { s = s * __expf(m - e) + 1.f; m = e; }
        else       { s += __expf(e - m); }
    }
    #pragma unroll
    for (int off = 16; off > 0; off >>= 1) {
        float mo = __shfl_xor_sync(0xffffffffu, m, off);
        float so = __shfl_xor_sync(0xffffffffu, s, off);
        float mn = fmaxf(m, mo);
        s = s * __expf(m - mn) + so * __expf(mo - mn);
        m = mn;
    }
    float inv = 1.f / (s + 1e-16f);

    // --- gather pass; lane owns channel pair (lane, lane+32) ---
    float w_self = __expf(e_self - m) * inv;
    float2 vself = g_hp2[(size_t)node * 32 + lane];
    float2 acc = make_float2(w_self * vself.x, w_self * vself.y);

    // chunk 0 from registers (no reload / re-exp)
    {
        int cnt0 = min(32, end - start);
        if (cnt0 > 0) {
            float w = (j0lane < end) ? __expf(e_c - m) * inv : 0.f;
            gather32(w, src_c, cnt0, lane, acc);
        }
    }
    // remaining chunks (rare: deg > 32)
    for (int j0 = start + 32; j0 < end; j0 += 32) {
        int jj = j0 + lane;
        int cnt = min(32, end - j0);
        int src = 0; float w = 0.f;
        if (jj < end) {
            src = __ldg(&g_esrc[jj]);
            w = __expf(leaky(g_as[src] + ad_n) - m) * inv;
        }
        gather32(w, src, cnt, lane, acc);
    }

    float o0 = acc.x + __ldg(&bias[lane]);
    float o1 = acc.y + __ldg(&bias[lane + 32]);
    o0 = o0 > 0.f ? o0 : 0.f;
    o1 = o1 > 0.f ? o1 : 0.f;
    if (to_ext) {
        out_ext[(size_t)node * 64 + lane]      = o0;
        out_ext[(size_t)node * 64 + 32 + lane] = o1;
    } else {
        g_h2[(size_t)node * 32 + lane] = make_float2(o0, o1);
    }
}

// ---------------- host launcher ----------------
extern "C" void kernel_launch(void* const* d_in, const int* in_sizes, int n_in,
                              void* d_out, int out_size) {
    const float* x  = (const float*)d_in[0];
    const int*   ei = (const int*)  d_in[1];
    const float* W0 = (const float*)d_in[4];
    const float* as0 = (const float*)d_in[5];
    const float* ad0 = (const float*)d_in[6];
    const float* b0  = (const float*)d_in[7];
    const float* W1 = (const float*)d_in[8];
    const float* as1 = (const float*)d_in[9];
    const float* ad1 = (const float*)d_in[10];
    const float* b1  = (const float*)d_in[11];
    const float* W2 = (const float*)d_in[12];
    const float* as2 = (const float*)d_in[13];
    const float* ad2 = (const float*)d_in[14];
    const float* b2  = (const float*)d_in[15];

    int n = in_sizes[0] / CIN0;
    int E = in_sizes[1] / 2;
    float* out = (float*)d_out;

    void* degp = nullptr;
    cudaGetSymbolAddress(&degp, g_deg);
    float2* h2 = nullptr;
    cudaGetSymbolAddress((void**)&h2, g_h2);

    cudaMemsetAsync(degp, 0, (size_t)n * sizeof(int), 0);

    dim3 gblock(32, 8);
    int ggrid = (n + 31) / 32;
    int cgrid = (E + 1023) / 1024;
    int wgrid = (n + 7) / 8;

    // layer 0 GEMM + fused degree count
    gemm_alpha_kernel<<<ggrid + cgrid, gblock>>>((const float4*)x, W0, as0, ad0,
                                                 n, CIN0, 0, ei, E, ggrid);
    scan_kernel   <<<1, 1024>>>(n);
    scatter_kernel<<<(E + 511) / 512, 256>>>(ei, E);
    aggregate_kernel<<<wgrid, 256>>>(b0, nullptr, 0, n);

    gemm_alpha_kernel<<<ggrid, gblock>>>((const float4*)h2, W1, as1, ad1,
                                         n, COUT, 1, nullptr, 0, ggrid);
    aggregate_kernel<<<wgrid, 256>>>(b1, nullptr, 0, n);

    gemm_alpha_kernel<<<ggrid, gblock>>>((const float4*)h2, W2, as2, ad2,
                                         n, COUT, 1, nullptr, 0, ggrid);
    aggregate_kernel<<<wgrid, 256>>>(b2, out, 1, n);
}

// round 6
// speedup vs baseline: 1.5441x; 1.1705x over previous
#include <cuda_runtime.h>
#include <math.h>

#define MAXN 50000
#define MAXE 800000
#define CIN0 128
#define COUT 64
#define NEG_SLOPE 0.2f

// ---------------- device scratch (double-buffered) ----------------
__device__ float2 g_hpA[MAXN * 32];    // permuted: pos p = channels (p, p+32)
__device__ float2 g_hpB[MAXN * 32];
__device__ float  g_asA[MAXN], g_adA[MAXN];
__device__ float  g_asB[MAXN], g_adB[MAXN];
__device__ int    g_rowptr[MAXN + 1];
__device__ int    g_deg[MAXN];
__device__ int    g_cnt[MAXN];
__device__ int    g_esrc[MAXE];

// ---------------- packed f32x2 helpers ----------------
__device__ __forceinline__ float2 ffma2(float2 a, float2 b, float2 c) {
    unsigned long long ra = *(unsigned long long*)&a;
    unsigned long long rb = *(unsigned long long*)&b;
    unsigned long long rc = *(unsigned long long*)&c;
    unsigned long long rd;
    asm("fma.rn.f32x2 %0, %1, %2, %3;" : "=l"(rd) : "l"(ra), "l"(rb), "l"(rc));
    return *(float2*)&rd;
}
__device__ __forceinline__ float2 dup2(float x) { return make_float2(x, x); }
__device__ __forceinline__ float leaky(float e) { return e > 0.f ? e : NEG_SLOPE * e; }

// ---------------- 16-lane gather (group mask!) ----------------
__device__ __forceinline__ void gather16(unsigned gmask, float w, int src, int cnt,
                                         int lane16, const float2* __restrict__ hp,
                                         float2& accA, float2& accB) {
    int t = 0;
    for (; t + 1 < cnt; t += 2) {
        float wa = __shfl_sync(gmask, w, t, 16);
        float wb = __shfl_sync(gmask, w, t + 1, 16);
        int   ia = __shfl_sync(gmask, src, t, 16);
        int   ib = __shfl_sync(gmask, src, t + 1, 16);
        float4 va = ((const float4*)&hp[(size_t)ia * 32])[lane16];
        float4 vb = ((const float4*)&hp[(size_t)ib * 32])[lane16];
        accA = ffma2(dup2(wa), make_float2(va.x, va.y), accA);
        accB = ffma2(dup2(wa), make_float2(va.z, va.w), accB);
        accA = ffma2(dup2(wb), make_float2(vb.x, vb.y), accA);
        accB = ffma2(dup2(wb), make_float2(vb.z, vb.w), accB);
    }
    if (t < cnt) {
        float wa = __shfl_sync(gmask, w, t, 16);
        int   ia = __shfl_sync(gmask, src, t, 16);
        float4 va = ((const float4*)&hp[(size_t)ia * 32])[lane16];
        accA = ffma2(dup2(wa), make_float2(va.x, va.y), accA);
        accB = ffma2(dup2(wa), make_float2(va.z, va.w), accB);
    }
}

// ---------------- per-node GAT aggregation, 16-lane group ----------------
__device__ __forceinline__ float4 agg_node(unsigned gmask,
                                           const float2* __restrict__ hp,
                                           const float* __restrict__ as,
                                           const float* __restrict__ ad,
                                           int node, int lane16) {
    int start = g_rowptr[node];
    int end   = g_rowptr[node + 1];
    float ad_n = __ldg(&ad[node]);
    float e_self = leaky(__ldg(&as[node]) + ad_n);

    // online softmax; cache first 2 chunks (deg<=32) in registers
    float m = (lane16 == 0) ? e_self : -1e30f;
    float s = (lane16 == 0) ? 1.f : 0.f;
    int j0 = start + lane16;
    int j1 = j0 + 16;
    int s0c = 0, s1c = 0;
    float e0c = 0.f, e1c = 0.f;
    if (j0 < end) {
        s0c = __ldg(&g_esrc[j0]);
        e0c = leaky(__ldg(&as[s0c]) + ad_n);
        if (e0c > m) { s = s * __expf(m - e0c) + 1.f; m = e0c; } else { s += __expf(e0c - m); }
    }
    if (j1 < end) {
        s1c = __ldg(&g_esrc[j1]);
        e1c = leaky(__ldg(&as[s1c]) + ad_n);
        if (e1c > m) { s = s * __expf(m - e1c) + 1.f; m = e1c; } else { s += __expf(e1c - m); }
    }
    for (int j = j1 + 16; j < end; j += 16) {
        float e = leaky(__ldg(&as[__ldg(&g_esrc[j])]) + ad_n);
        if (e > m) { s = s * __expf(m - e) + 1.f; m = e; } else { s += __expf(e - m); }
    }
    #pragma unroll
    for (int off = 8; off > 0; off >>= 1) {
        float mo = __shfl_xor_sync(gmask, m, off, 16);
        float so = __shfl_xor_sync(gmask, s, off, 16);
        float mn = fmaxf(m, mo);
        s = s * __expf(m - mn) + so * __expf(mo - mn);
        m = mn;
    }
    float inv = 1.f / (s + 1e-16f);

    // gather
    float w_self = __expf(e_self - m) * inv;
    float4 vs = ((const float4*)&hp[(size_t)node * 32])[lane16];
    float2 accA = make_float2(w_self * vs.x, w_self * vs.y);
    float2 accB = make_float2(w_self * vs.z, w_self * vs.w);

    int deg = end - start;
    int c0 = min(16, deg);
    if (c0 > 0) {
        float w0 = (j0 < end) ? __expf(e0c - m) * inv : 0.f;
        gather16(gmask, w0, s0c, c0, lane16, hp, accA, accB);
    }
    if (deg > 16) {
        int c1 = min(16, deg - 16);
        float w1 = (j1 < end) ? __expf(e1c - m) * inv : 0.f;
        gather16(gmask, w1, s1c, c1, lane16, hp, accA, accB);
    }
    for (int jb = start + 32; jb < end; jb += 16) {   // rare: deg > 32
        int jj = jb + lane16;
        int c = min(16, end - jb);
        int sj = 0; float w = 0.f;
        if (jj < end) {
            sj = __ldg(&g_esrc[jj]);
            w = __expf(leaky(__ldg(&as[sj]) + ad_n) - m) * inv;
        }
        gather16(gmask, w, sj, c, lane16, hp, accA, accB);
    }
    return make_float4(accA.x, accA.y, accB.x, accB.y);
}

// bias (permuted float4 channel order: 2l, 2l+32, 2l+1, 2l+33) + relu
__device__ __forceinline__ float4 bias_relu(float4 v, const float* __restrict__ bias, int lane16) {
    v.x = fmaxf(v.x + __ldg(&bias[2 * lane16]),      0.f);
    v.y = fmaxf(v.y + __ldg(&bias[2 * lane16 + 32]), 0.f);
    v.z = fmaxf(v.z + __ldg(&bias[2 * lane16 + 1]),  0.f);
    v.w = fmaxf(v.w + __ldg(&bias[2 * lane16 + 33]), 0.f);
    return v;
}

// ---------------- layer-0 GEMM + fused alpha + fused degree count ----------------
__global__ void gemm_alpha_kernel(const float4* __restrict__ X,
                                  const float* __restrict__ W,
                                  const float* __restrict__ a_src,
                                  const float* __restrict__ a_dst,
                                  float2* __restrict__ hp_out,
                                  float* __restrict__ as_out,
                                  float* __restrict__ ad_out,
                                  int n, const int* __restrict__ ei, int E, int ggrid) {
    if (blockIdx.x >= ggrid) {
        int base = (blockIdx.x - ggrid) * 1024 + (threadIdx.y * 32 + threadIdx.x);
        #pragma unroll
        for (int u = 0; u < 4; u++) {
            int i = base + u * 256;
            if (i < E) atomicAdd(&g_deg[__ldg(&ei[E + i])], 1);
        }
        return;
    }

    __shared__ float2 Ws2[CIN0 * 32];
    int tx = threadIdx.x, ty = threadIdx.y;
    int tid = ty * 32 + tx;
    for (int idx = tid; idx < CIN0 * 32; idx += 256) {
        int k = idx >> 5, c = idx & 31;
        Ws2[idx] = make_float2(W[k * 64 + c], W[k * 64 + c + 32]);
    }
    __syncthreads();

    int row0 = blockIdx.x * 32 + ty * 4;
    int r0 = min(row0 + 0, n - 1), r1 = min(row0 + 1, n - 1);
    int r2 = min(row0 + 2, n - 1), r3 = min(row0 + 3, n - 1);
    const float4* x0 = X + (size_t)r0 * 32;
    const float4* x1 = X + (size_t)r1 * 32;
    const float4* x2 = X + (size_t)r2 * 32;
    const float4* x3 = X + (size_t)r3 * 32;

    float2 acc0 = make_float2(0.f, 0.f), acc1 = make_float2(0.f, 0.f);
    float2 acc2 = make_float2(0.f, 0.f), acc3 = make_float2(0.f, 0.f);
    for (int k4 = 0; k4 < 32; k4++) {
        float4 v0 = x0[k4], v1 = x1[k4], v2 = x2[k4], v3 = x3[k4];
        int kb = k4 * 128 + tx;
        float2 wA = Ws2[kb], wB = Ws2[kb + 32], wC = Ws2[kb + 64], wD = Ws2[kb + 96];
        acc0 = ffma2(dup2(v0.x), wA, acc0); acc1 = ffma2(dup2(v1.x), wA, acc1);
        acc2 = ffma2(dup2(v2.x), wA, acc2); acc3 = ffma2(dup2(v3.x), wA, acc3);
        acc0 = ffma2(dup2(v0.y), wB, acc0); acc1 = ffma2(dup2(v1.y), wB, acc1);
        acc2 = ffma2(dup2(v2.y), wB, acc2); acc3 = ffma2(dup2(v3.y), wB, acc3);
        acc0 = ffma2(dup2(v0.z), wC, acc0); acc1 = ffma2(dup2(v1.z), wC, acc1);
        acc2 = ffma2(dup2(v2.z), wC, acc2); acc3 = ffma2(dup2(v3.z), wC, acc3);
        acc0 = ffma2(dup2(v0.w), wD, acc0); acc1 = ffma2(dup2(v1.w), wD, acc1);
        acc2 = ffma2(dup2(v2.w), wD, acc2); acc3 = ffma2(dup2(v3.w), wD, acc3);
    }

    if (row0 + 0 < n) hp_out[(size_t)(row0 + 0) * 32 + tx] = acc0;
    if (row0 + 1 < n) hp_out[(size_t)(row0 + 1) * 32 + tx] = acc1;
    if (row0 + 2 < n) hp_out[(size_t)(row0 + 2) * 32 + tx] = acc2;
    if (row0 + 3 < n) hp_out[(size_t)(row0 + 3) * 32 + tx] = acc3;

    float asA = __ldg(&a_src[tx]), asB = __ldg(&a_src[tx + 32]);
    float adA = __ldg(&a_dst[tx]), adB = __ldg(&a_dst[tx + 32]);
    float s0 = acc0.x * asA + acc0.y * asB, s1 = acc1.x * asA + acc1.y * asB;
    float s2 = acc2.x * asA + acc2.y * asB, s3 = acc3.x * asA + acc3.y * asB;
    float d0 = acc0.x * adA + acc0.y * adB, d1 = acc1.x * adA + acc1.y * adB;
    float d2 = acc2.x * adA + acc2.y * adB, d3 = acc3.x * adA + acc3.y * adB;
    #pragma unroll
    for (int off = 16; off > 0; off >>= 1) {
        s0 += __shfl_xor_sync(0xffffffffu, s0, off); s1 += __shfl_xor_sync(0xffffffffu, s1, off);
        s2 += __shfl_xor_sync(0xffffffffu, s2, off); s3 += __shfl_xor_sync(0xffffffffu, s3, off);
        d0 += __shfl_xor_sync(0xffffffffu, d0, off); d1 += __shfl_xor_sync(0xffffffffu, d1, off);
        d2 += __shfl_xor_sync(0xffffffffu, d2, off); d3 += __shfl_xor_sync(0xffffffffu, d3, off);
    }
    if (tx == 0) {
        if (row0 + 0 < n) { as_out[row0 + 0] = s0; ad_out[row0 + 0] = d0; }
        if (row0 + 1 < n) { as_out[row0 + 1] = s1; ad_out[row0 + 1] = d1; }
        if (row0 + 2 < n) { as_out[row0 + 2] = s2; ad_out[row0 + 2] = d2; }
        if (row0 + 3 < n) { as_out[row0 + 3] = s3; ad_out[row0 + 3] = d3; }
    }
}

// ---------------- fused: aggregate(prev) -> smem -> GEMM + alpha (next) ----------------
__global__ void __launch_bounds__(256, 6)
agg_gemm_kernel(const float2* __restrict__ hp_in,
                const float* __restrict__ as_in, const float* __restrict__ ad_in,
                const float* __restrict__ bias,
                const float* __restrict__ W,
                const float* __restrict__ a_src, const float* __restrict__ a_dst,
                float2* __restrict__ hp_out,
                float* __restrict__ as_out, float* __restrict__ ad_out, int n) {
    __shared__ float2 Ws2[COUT * 32];   // 16 KB
    __shared__ float4 Hs4[32 * 16];     //  8 KB aggregated h (permuted)

    int tid = threadIdx.x;
    int warp = tid >> 5, lane = tid & 31;
    int g = lane >> 4, lane16 = lane & 15;
    unsigned gmask = 0xFFFFu << (g << 4);
    int node0 = blockIdx.x * 32;

    for (int idx = tid; idx < COUT * 32; idx += 256) {
        int k = idx >> 5, c = idx & 31;
        int kk = (k >> 1) + ((k & 1) << 5);
        Ws2[idx] = make_float2(W[kk * 64 + c], W[kk * 64 + c + 32]);
    }

    // aggregate phase: warp -> 4 nodes, two per pass (one per 16-lane group)
    #pragma unroll
    for (int r = 0; r < 2; r++) {
        int node = node0 + warp * 4 + r * 2 + g;
        float4 v = make_float4(0.f, 0.f, 0.f, 0.f);
        if (node < n) {
            v = agg_node(gmask, hp_in, as_in, ad_in, node, lane16);
            v = bias_relu(v, bias, lane16);
        }
        Hs4[(warp * 4 + r * 2 + g) * 16 + lane16] = v;
    }
    __syncthreads();

    // GEMM phase
    int tx = lane, ty = warp;
    int row0 = node0 + ty * 4;
    const float4* x0 = &Hs4[(ty * 4 + 0) * 16];
    const float4* x1 = &Hs4[(ty * 4 + 1) * 16];
    const float4* x2 = &Hs4[(ty * 4 + 2) * 16];
    const float4* x3 = &Hs4[(ty * 4 + 3) * 16];

    float2 acc0 = make_float2(0.f, 0.f), acc1 = make_float2(0.f, 0.f);
    float2 acc2 = make_float2(0.f, 0.f), acc3 = make_float2(0.f, 0.f);
    #pragma unroll 4
    for (int k4 = 0; k4 < 16; k4++) {
        float4 v0 = x0[k4], v1 = x1[k4], v2 = x2[k4], v3 = x3[k4];
        int kb = k4 * 128 + tx;
        float2 wA = Ws2[kb], wB = Ws2[kb + 32], wC = Ws2[kb + 64], wD = Ws2[kb + 96];
        acc0 = ffma2(dup2(v0.x), wA, acc0); acc1 = ffma2(dup2(v1.x), wA, acc1);
        acc2 = ffma2(dup2(v2.x), wA, acc2); acc3 = ffma2(dup2(v3.x), wA, acc3);
        acc0 = ffma2(dup2(v0.y), wB, acc0); acc1 = ffma2(dup2(v1.y), wB, acc1);
        acc2 = ffma2(dup2(v2.y), wB, acc2); acc3 = ffma2(dup2(v3.y), wB, acc3);
        acc0 = ffma2(dup2(v0.z), wC, acc0); acc1 = ffma2(dup2(v1.z), wC, acc1);
        acc2 = ffma2(dup2(v2.z), wC, acc2); acc3 = ffma2(dup2(v3.z), wC, acc3);
        acc0 = ffma2(dup2(v0.w), wD, acc0); acc1 = ffma2(dup2(v1.w), wD, acc1);
        acc2 = ffma2(dup2(v2.w), wD, acc2); acc3 = ffma2(dup2(v3.w), wD, acc3);
    }

    if (row0 + 0 < n) hp_out[(size_t)(row0 + 0) * 32 + tx] = acc0;
    if (row0 + 1 < n) hp_out[(size_t)(row0 + 1) * 32 + tx] = acc1;
    if (row0 + 2 < n) hp_out[(size_t)(row0 + 2) * 32 + tx] = acc2;
    if (row0 + 3 < n) hp_out[(size_t)(row0 + 3) * 32 + tx] = acc3;

    float asA = __ldg(&a_src[tx]), asB = __ldg(&a_src[tx + 32]);
    float adA = __ldg(&a_dst[tx]), adB = __ldg(&a_dst[tx + 32]);
    float s0 = acc0.x * asA + acc0.y * asB, s1 = acc1.x * asA + acc1.y * asB;
    float s2 = acc2.x * asA + acc2.y * asB, s3 = acc3.x * asA + acc3.y * asB;
    float d0 = acc0.x * adA + acc0.y * adB, d1 = acc1.x * adA + acc1.y * adB;
    float d2 = acc2.x * adA + acc2.y * adB, d3 = acc3.x * adA + acc3.y * adB;
    #pragma unroll
    for (int off = 16; off > 0; off >>= 1) {
        s0 += __shfl_xor_sync(0xffffffffu, s0, off); s1 += __shfl_xor_sync(0xffffffffu, s1, off);
        s2 += __shfl_xor_sync(0xffffffffu, s2, off); s3 += __shfl_xor_sync(0xffffffffu, s3, off);
        d0 += __shfl_xor_sync(0xffffffffu, d0, off); d1 += __shfl_xor_sync(0xffffffffu, d1, off);
        d2 += __shfl_xor_sync(0xffffffffu, d2, off); d3 += __shfl_xor_sync(0xffffffffu, d3, off);
    }
    if (tx == 0) {
        if (row0 + 0 < n) { as_out[row0 + 0] = s0; ad_out[row0 + 0] = d0; }
        if (row0 + 1 < n) { as_out[row0 + 1] = s1; ad_out[row0 + 1] = d1; }
        if (row0 + 2 < n) { as_out[row0 + 2] = s2; ad_out[row0 + 2] = d2; }
        if (row0 + 3 < n) { as_out[row0 + 3] = s3; ad_out[row0 + 3] = d3; }
    }
}

// ---------------- final aggregate -> external output ----------------
__global__ void __launch_bounds__(256, 8)
agg_out_kernel(const float2* __restrict__ hp_in,
               const float* __restrict__ as_in, const float* __restrict__ ad_in,
               const float* __restrict__ bias, float* __restrict__ out, int n) {
    int tid = threadIdx.x;
    int warp = tid >> 5, lane = tid & 31;
    int g = lane >> 4, lane16 = lane & 15;
    unsigned gmask = 0xFFFFu << (g << 4);
    int node = blockIdx.x * 16 + warp * 2 + g;
    if (node >= n) return;
    float4 v = agg_node(gmask, hp_in, as_in, ad_in, node, lane16);
    v = bias_relu(v, bias, lane16);
    float* o = out + (size_t)node * 64;
    ((float2*)o)[lane16]        = make_float2(v.x, v.z);   // ch 2l, 2l+1
    ((float2*)(o + 32))[lane16] = make_float2(v.y, v.w);   // ch 2l+32, 2l+33
}

// ---------------- CSR scan + scatter ----------------
__global__ void scan_kernel(int n) {
    __shared__ int wsum[32];
    __shared__ int carry_s;
    int t = threadIdx.x, lane = t & 31, wid = t >> 5;
    if (t == 0) carry_s = 0;
    __syncthreads();
    for (int base = 0; base < n; base += 1024) {
        int i = base + t;
        int v = (i < n) ? g_deg[i] : 0;
        int s = v;
        #pragma unroll
        for (int off = 1; off < 32; off <<= 1) {
            int u = __shfl_up_sync(0xffffffffu, s, off);
            if (lane >= off) s += u;
        }
        if (lane == 31) wsum[wid] = s;
        __syncthreads();
        if (wid == 0) {
            int ws = wsum[lane];
            #pragma unroll
            for (int off = 1; off < 32; off <<= 1) {
                int u = __shfl_up_sync(0xffffffffu, ws, off);
                if (lane >= off) ws += u;
            }
            wsum[lane] = ws;
        }
        __syncthreads();
        int woff = (wid > 0) ? wsum[wid - 1] : 0;
        int carry = carry_s;
        int excl = carry + woff + s - v;
        if (i < n) { g_rowptr[i] = excl; g_cnt[i] = excl; }
        __syncthreads();
        if (t == 1023) carry_s = carry + woff + s;
        __syncthreads();
    }
    if (t == 0) g_rowptr[n] = carry_s;
}

__global__ void scatter_kernel(const int* __restrict__ ei, int E) {
    int base = (blockIdx.x * blockDim.x + threadIdx.x) * 2;
    #pragma unroll
    for (int u = 0; u < 2; u++) {
        int i = base + u;
        if (i < E) {
            int src = __ldg(&ei[i]);
            int dst = __ldg(&ei[E + i]);
            int pos = atomicAdd(&g_cnt[dst], 1);
            g_esrc[pos] = src;
        }
    }
}

// ---------------- host launcher ----------------
extern "C" void kernel_launch(void* const* d_in, const int* in_sizes, int n_in,
                              void* d_out, int out_size) {
    const float* x  = (const float*)d_in[0];
    const int*   ei = (const int*)  d_in[1];
    const float* W0 = (const float*)d_in[4];
    const float* av_s0 = (const float*)d_in[5];
    const float* av_d0 = (const float*)d_in[6];
    const float* b0  = (const float*)d_in[7];
    const float* W1 = (const float*)d_in[8];
    const float* av_s1 = (const float*)d_in[9];
    const float* av_d1 = (const float*)d_in[10];
    const float* b1  = (const float*)d_in[11];
    const float* W2 = (const float*)d_in[12];
    const float* av_s2 = (const float*)d_in[13];
    const float* av_d2 = (const float*)d_in[14];
    const float* b2  = (const float*)d_in[15];

    int n = in_sizes[0] / CIN0;
    int E = in_sizes[1] / 2;
    float* out = (float*)d_out;

    void *degp, *hpA, *hpB, *asA, *adA, *asB, *adB;
    cudaGetSymbolAddress(&degp, g_deg);
    cudaGetSymbolAddress(&hpA, g_hpA);
    cudaGetSymbolAddress(&hpB, g_hpB);
    cudaGetSymbolAddress(&asA, g_asA);
    cudaGetSymbolAddress(&adA, g_adA);
    cudaGetSymbolAddress(&asB, g_asB);
    cudaGetSymbolAddress(&adB, g_adB);

    cudaMemsetAsync(degp, 0, (size_t)n * sizeof(int), 0);

    dim3 gblock(32, 8);
    int ggrid = (n + 31) / 32;
    int cgrid = (E + 1023) / 1024;

    // layer 0: GEMM(x,W0)+alpha0 -> buf A   (+ fused degree count)
    gemm_alpha_kernel<<<ggrid + cgrid, gblock>>>((const float4*)x, W0, av_s0, av_d0,
                                                 (float2*)hpA, (float*)asA, (float*)adA,
                                                 n, ei, E, ggrid);
    scan_kernel   <<<1, 1024>>>(n);
    scatter_kernel<<<(E + 511) / 512, 256>>>(ei, E);

    // agg(L0, A) + GEMM(W1) + alpha1 -> buf B
    agg_gemm_kernel<<<ggrid, 256>>>((const float2*)hpA, (const float*)asA, (const float*)adA,
                                    b0, W1, av_s1, av_d1,
                                    (float2*)hpB, (float*)asB, (float*)adB, n);
    // agg(L1, B) + GEMM(W2) + alpha2 -> buf A
    agg_gemm_kernel<<<ggrid, 256>>>((const float2*)hpB, (const float*)asB, (const float*)adB,
                                    b1, W2, av_s2, av_d2,
                                    (float2*)hpA, (float*)asA, (float*)adA, n);
    // final aggregate -> out
    agg_out_kernel<<<(n + 15) / 16, 256>>>((const float2*)hpA, (const float*)asA,
                                           (const float*)adA, b2, out, n);
}